// round 1
// baseline (speedup 1.0000x reference)
#include <cuda_runtime.h>
#include <cstdint>

// ============================================================================
// FourierKARTLayer: V[b,s,d] = sum_{q,k} A[d,q,k] * sin(k*(C_q + w_q*t) + Bp[d,q,k])
//   C = X0 @ Wc_w^T + Wc_b
// Decomposed:
//   W2[(kk*128+q), d] = A[d,q,k]*cos(Bp)  (kk=k-1 in 0..5,  sin-part)
//                     = A[d,q,k]*sin(Bp)  (kk=k+5 in 6..11, cos-part)
//   F[token, kk*128+q] = sin(k*angle) / cos(k*angle)  via sincos + recurrence
//   V = F @ W2
// ============================================================================

#define D_INF   256
#define D_OUTF  64
#define NQ      128
#define NK      6
#define NTOK    2048
#define SEQ     1024
#define TPB     256
#define TOKB    8          // tokens per block
#define NFEAT   1536       // 12 * 128
#define FPAD    12         // floats per F_s row (8 tokens + 4 pad, keeps 8B align, 4-way max conflict)

__device__ float g_WcT[D_INF * NQ];     // [i][q]  (q contiguous)
__device__ float g_W2[NFEAT * D_OUTF];  // [f][d]  (d contiguous)

using u64 = unsigned long long;

__device__ __forceinline__ u64 pack2(float x, float y) {
    u64 r; asm("mov.b64 %0, {%1, %2};" : "=l"(r) : "f"(x), "f"(y)); return r;
}
__device__ __forceinline__ u64 fma2(u64 a, u64 b, u64 c) {
    u64 d; asm("fma.rn.f32x2 %0, %1, %2, %3;" : "=l"(d) : "l"(a), "l"(b), "l"(c)); return d;
}
__device__ __forceinline__ float2 unpack2(u64 a) {
    float2 f; asm("mov.b64 {%0, %1}, %2;" : "=f"(f.x), "=f"(f.y) : "l"(a)); return f;
}

// ----------------------------------------------------------------------------
// Prep: fold Bp into W2 = A*cos(Bp) / A*sin(Bp); transpose Wc.
// ----------------------------------------------------------------------------
__global__ void prep_kernel(const float* __restrict__ Wc_w,
                            const float* __restrict__ A,
                            const float* __restrict__ Bp) {
    int n = blockIdx.x * blockDim.x + threadIdx.x;
    if (n < NFEAT * D_OUTF) {
        int d  = n & (D_OUTF - 1);
        int f  = n >> 6;
        int q  = f & (NQ - 1);
        int kk = f >> 7;                       // 0..11
        int k  = (kk >= NK) ? (kk - NK) : kk;  // 0..5
        int src = (d * NQ + q) * NK + k;
        float a  = A[src];
        float bp = Bp[src];
        // range-reduce to [-pi, pi] then fast sincos
        float nr = rintf(bp * 0.15915494309189535f);
        float br = fmaf(nr, -6.283185307179586f, bp);
        float sb, cb;
        __sincosf(br, &sb, &cb);
        g_W2[n] = (kk < NK) ? (a * cb) : (a * sb);
    }
    if (n < D_INF * NQ) {
        int q = n & (NQ - 1);
        int i = n >> 7;
        g_WcT[n] = Wc_w[q * D_INF + i];
    }
}

// ----------------------------------------------------------------------------
// Main fused kernel: 256 blocks x 8 tokens, 256 threads.
// ----------------------------------------------------------------------------
__global__ void __launch_bounds__(TPB, 2) main_kernel(
    const float* __restrict__ X0,
    const float* __restrict__ t,
    const float* __restrict__ Wc_b,
    const float* __restrict__ w,
    float* __restrict__ V) {

    extern __shared__ float smem[];
    float* XT = smem;                       // [256][8]   (i-major, token contiguous)
    float* Fs = smem + D_INF * TOKB;        // [1536][12] (row = kk*128+q, cols 0..7 = tokens)

    const int tid = threadIdx.x;
    const int g0  = blockIdx.x * TOKB;      // first token of block (all in same batch: 8 | 1024)
    const float tb = t[g0 / SEQ];

    // ---- Phase A: load + transpose X tile -------------------------------
    {
        int tk  = tid >> 5;       // token 0..7
        int seg = tid & 31;       // 0..31, each covers 8 features
        const float4* src = (const float4*)(X0 + (size_t)(g0 + tk) * D_INF + seg * 8);
        float4 v0 = src[0];
        float4 v1 = src[1];
        int i0 = seg * 8;
        XT[(i0 + 0) * TOKB + tk] = v0.x;
        XT[(i0 + 1) * TOKB + tk] = v0.y;
        XT[(i0 + 2) * TOKB + tk] = v0.z;
        XT[(i0 + 3) * TOKB + tk] = v0.w;
        XT[(i0 + 4) * TOKB + tk] = v1.x;
        XT[(i0 + 5) * TOKB + tk] = v1.y;
        XT[(i0 + 6) * TOKB + tk] = v1.z;
        XT[(i0 + 7) * TOKB + tk] = v1.w;
    }
    __syncthreads();

    // ---- Phase B: GEMM1 (angles) + sincos + harmonic recurrence ---------
    {
        const int q = tid & (NQ - 1);
        const int h = tid >> 7;              // token half: tokens h*4 .. h*4+3
        float init = fmaf(w[q], tb, Wc_b[q]);   // bias + w_q * t  (folded into accumulator)
        u64 acc0 = pack2(init, init);
        u64 acc1 = pack2(init, init);
        const float* wp = g_WcT + q;
        const u64* xb = (const u64*)(XT + h * 4);   // pairs (h*4,h*4+1) and (h*4+2,h*4+3)

        #pragma unroll 8
        for (int i = 0; i < D_INF; i++) {
            float wv = wp[i * NQ];
            u64 wd = pack2(wv, wv);
            u64 x01 = xb[i * (TOKB / 2)];
            u64 x23 = xb[i * (TOKB / 2) + 1];
            acc0 = fma2(x01, wd, acc0);
            acc1 = fma2(x23, wd, acc1);
        }

        float2 a01 = unpack2(acc0);
        float2 a23 = unpack2(acc1);
        float ang[4] = {a01.x, a01.y, a23.x, a23.y};

        #pragma unroll
        for (int j = 0; j < 4; j++) {
            int tk = h * 4 + j;
            float a = ang[j];
            // range-reduce base angle, then recurrence gives exact harmonics
            float nr = rintf(a * 0.15915494309189535f);
            float ar = fmaf(nr, -6.283185307179586f, a);
            float s1, c1;
            __sincosf(ar, &s1, &c1);
            float sk = s1, ck = c1;
            #pragma unroll
            for (int k = 0; k < NK; k++) {
                Fs[(k * NQ + q) * FPAD + tk]        = sk;   // sin(k+1 harmonic)
                Fs[((k + NK) * NQ + q) * FPAD + tk] = ck;   // cos(k+1 harmonic)
                float ns = fmaf(sk, c1, ck * s1);
                float nc = fmaf(ck, c1, -sk * s1);
                sk = ns; ck = nc;
            }
        }
    }
    __syncthreads();

    // ---- Phase C: GEMM2  V = F @ W2, f32x2-packed over token pairs ------
    const int dg = tid & 15;     // d-group: d = dg*4 .. dg*4+3
    const int fs = tid >> 4;     // f-slice 0..15, covers 96 features each
    u64 acc[4][4];               // [dd][token-pair]
    #pragma unroll
    for (int a = 0; a < 4; a++)
        #pragma unroll
        for (int b = 0; b < 4; b++) acc[a][b] = 0ULL;

    const float4* w2p = (const float4*)g_W2;
    #pragma unroll 4
    for (int ff = 0; ff < NFEAT / 16; ff++) {
        int f = fs * (NFEAT / 16) + ff;
        float4 wv = w2p[f * (D_OUTF / 4) + dg];       // W2[f][dg*4 .. +3], LDG.128 coalesced
        u64 wd0 = pack2(wv.x, wv.x);
        u64 wd1 = pack2(wv.y, wv.y);
        u64 wd2 = pack2(wv.z, wv.z);
        u64 wd3 = pack2(wv.w, wv.w);
        const u64* fp = (const u64*)(Fs + f * FPAD);  // 4 token pairs, broadcast LDS.64
        u64 p0 = fp[0], p1 = fp[1], p2 = fp[2], p3 = fp[3];
        acc[0][0] = fma2(p0, wd0, acc[0][0]);
        acc[0][1] = fma2(p1, wd0, acc[0][1]);
        acc[0][2] = fma2(p2, wd0, acc[0][2]);
        acc[0][3] = fma2(p3, wd0, acc[0][3]);
        acc[1][0] = fma2(p0, wd1, acc[1][0]);
        acc[1][1] = fma2(p1, wd1, acc[1][1]);
        acc[1][2] = fma2(p2, wd1, acc[1][2]);
        acc[1][3] = fma2(p3, wd1, acc[1][3]);
        acc[2][0] = fma2(p0, wd2, acc[2][0]);
        acc[2][1] = fma2(p1, wd2, acc[2][1]);
        acc[2][2] = fma2(p2, wd2, acc[2][2]);
        acc[2][3] = fma2(p3, wd2, acc[2][3]);
        acc[3][0] = fma2(p0, wd3, acc[3][0]);
        acc[3][1] = fma2(p1, wd3, acc[3][1]);
        acc[3][2] = fma2(p2, wd3, acc[3][2]);
        acc[3][3] = fma2(p3, wd3, acc[3][3]);
    }

    // ---- Reduce over the 16 f-slices via smem ---------------------------
    __syncthreads();                 // F reads done; reuse smem
    float* R = smem;                 // [16][512] partials
    #pragma unroll
    for (int dd = 0; dd < 4; dd++) {
        int d = dg * 4 + dd;
        #pragma unroll
        for (int p = 0; p < 4; p++) {
            float2 v = unpack2(acc[dd][p]);
            R[fs * 512 + (2 * p)     * D_OUTF + d] = v.x;
            R[fs * 512 + (2 * p + 1) * D_OUTF + d] = v.y;
        }
    }
    __syncthreads();

    {
        float2 s = make_float2(0.f, 0.f);
        #pragma unroll
        for (int j = 0; j < 16; j++) {
            float2 r = *(const float2*)&R[j * 512 + 2 * tid];
            s.x += r.x;
            s.y += r.y;
        }
        ((float2*)(V + (size_t)g0 * D_OUTF))[tid] = s;
    }
}

// ----------------------------------------------------------------------------
extern "C" void kernel_launch(void* const* d_in, const int* in_sizes, int n_in,
                              void* d_out, int out_size) {
    const float* X0   = (const float*)d_in[0];
    const float* t    = (const float*)d_in[1];
    const float* Wc_w = (const float*)d_in[2];
    const float* Wc_b = (const float*)d_in[3];
    const float* w    = (const float*)d_in[4];
    const float* A    = (const float*)d_in[5];
    const float* Bp   = (const float*)d_in[6];
    float* V = (float*)d_out;

    const int smem_bytes = (D_INF * TOKB + NFEAT * FPAD) * (int)sizeof(float); // 81920
    cudaFuncSetAttribute(main_kernel, cudaFuncAttributeMaxDynamicSharedMemorySize, smem_bytes);

    prep_kernel<<<(NFEAT * D_OUTF + 255) / 256, 256>>>(Wc_w, A, Bp);
    main_kernel<<<NTOK / TOKB, TPB, smem_bytes>>>(X0, t, Wc_b, w, V);
}